// round 1
// baseline (speedup 1.0000x reference)
#include <cuda_runtime.h>
#include <math.h>

// Problem constants
#define Bv 2
#define Sv 2048
#define Dv 1024
#define Hv 16
#define HDv 64
#define Mv (Bv*Sv)   // 4096 rows

// Scratch (device globals: no allocation allowed)
__device__ float g_qkv[(size_t)Mv * 3 * Dv];   // [4096, 3072]
__device__ float g_o[(size_t)Mv * Dv];         // [4096, 1024] attention output

// ---------------------------------------------------------------------------
// SGEMM NT: C[M,N] = A[M,K] * B[N,K]^T   (A,B row-major, K contiguous in both)
// 128x128x16 tile, 256 threads, 8x8 per thread
// All dims divisible by tile sizes -> no bounds checks.
// ---------------------------------------------------------------------------
#define BM 128
#define BN 128
#define BKg 16
#define TM 8
#define TN 8

__global__ __launch_bounds__(256) void sgemm_nt(
    const float* __restrict__ A, const float* __restrict__ B,
    float* __restrict__ C, int K, int ldc)
{
    __shared__ float As[BKg][BM + 4];
    __shared__ float Bs[BKg][BN + 4];

    const int tid = threadIdx.x;
    const int bm = blockIdx.y * BM;
    const int bn = blockIdx.x * BN;
    const int tr = (tid >> 4) * TM;   // 0..120
    const int tc = (tid & 15) * TN;   // 0..120

    float acc[TM][TN] = {};

    for (int k0 = 0; k0 < K; k0 += BKg) {
        #pragma unroll
        for (int it = 0; it < 2; ++it) {
            int idx = tid + it * 256;        // 0..511
            int row = idx >> 2;              // 0..127
            int c4  = (idx & 3) * 4;         // 0,4,8,12
            float4 av = *(const float4*)(A + (size_t)(bm + row) * K + k0 + c4);
            As[c4 + 0][row] = av.x; As[c4 + 1][row] = av.y;
            As[c4 + 2][row] = av.z; As[c4 + 3][row] = av.w;
            float4 bv = *(const float4*)(B + (size_t)(bn + row) * K + k0 + c4);
            Bs[c4 + 0][row] = bv.x; Bs[c4 + 1][row] = bv.y;
            Bs[c4 + 2][row] = bv.z; Bs[c4 + 3][row] = bv.w;
        }
        __syncthreads();

        #pragma unroll
        for (int kk = 0; kk < BKg; ++kk) {
            float a[TM], b[TN];
            *(float4*)&a[0] = *(const float4*)&As[kk][tr];
            *(float4*)&a[4] = *(const float4*)&As[kk][tr + 4];
            *(float4*)&b[0] = *(const float4*)&Bs[kk][tc];
            *(float4*)&b[4] = *(const float4*)&Bs[kk][tc + 4];
            #pragma unroll
            for (int i = 0; i < TM; ++i)
                #pragma unroll
                for (int j = 0; j < TN; ++j)
                    acc[i][j] = fmaf(a[i], b[j], acc[i][j]);
        }
        __syncthreads();
    }

    #pragma unroll
    for (int i = 0; i < TM; ++i) {
        float* cp = C + (size_t)(bm + tr + i) * ldc + bn + tc;
        *(float4*)cp       = make_float4(acc[i][0], acc[i][1], acc[i][2], acc[i][3]);
        *(float4*)(cp + 4) = make_float4(acc[i][4], acc[i][5], acc[i][6], acc[i][7]);
    }
}

// ---------------------------------------------------------------------------
// Flash attention (fp32, causal). One block per (q-tile, head, batch).
// 64 queries x 64 keys per inner tile, HD=64. 256 threads as 16x16 grid,
// each owns a 4x4 fragment of S and of O.
// ---------------------------------------------------------------------------
#define BQ 64
#define BKV 64
#define QST 65     // row stride for Q/K/V tiles (conflict-friendly)
#define PST 68     // row stride for P tile (float4-store aligned)

#define ATTN_SMEM ((3 * BQ * QST + BQ * PST) * 4)   // 67328 bytes

__global__ __launch_bounds__(256) void attn_kernel(
    const float* __restrict__ qkv, float* __restrict__ out)
{
    extern __shared__ float sm[];
    float* Qs = sm;                   // [64][65]
    float* Ks = Qs + BQ * QST;        // [64][65]
    float* Vs = Ks + BKV * QST;       // [64][65]
    float* Ps = Vs + BKV * QST;       // [64][68]

    const int tid = threadIdx.x;
    const int tx = tid & 15;
    const int ty = tid >> 4;
    const int qb = blockIdx.x;        // 0..31
    const int h  = blockIdx.y;
    const int b  = blockIdx.z;
    const int qbase = qb * BQ;

    const size_t rstride = 3 * Dv;    // qkv row stride
    const float* qptr = qkv + ((size_t)b * Sv + qbase) * rstride + (size_t)h * HDv;
    const float* kptr = qkv + (size_t)b * Sv * rstride + Dv     + (size_t)h * HDv;
    const float* vptr = qkv + (size_t)b * Sv * rstride + 2 * Dv + (size_t)h * HDv;

    // Load + pre-scale Q (HD^-0.5 = 0.125)
    for (int idx = tid; idx < BQ * HDv; idx += 256) {
        int r = idx >> 6, d = idx & 63;
        Qs[r * QST + d] = qptr[(size_t)r * rstride + d] * 0.125f;
    }

    float o[4][4] = {};
    float m[4] = {-INFINITY, -INFINITY, -INFINITY, -INFINITY};
    float l[4] = {};

    __syncthreads();

    for (int j = 0; j <= qb; ++j) {
        const int kb = j * BKV;
        for (int idx = tid; idx < BKV * HDv; idx += 256) {
            int r = idx >> 6, d = idx & 63;
            Ks[r * QST + d] = kptr[(size_t)(kb + r) * rstride + d];
            Vs[r * QST + d] = vptr[(size_t)(kb + r) * rstride + d];
        }
        __syncthreads();

        // S = Q * K^T (4x4 fragment per thread)
        float s[4][4] = {};
        #pragma unroll 8
        for (int d = 0; d < HDv; ++d) {
            float a[4], kk[4];
            #pragma unroll
            for (int i = 0; i < 4; ++i)  a[i]  = Qs[(4 * ty + i) * QST + d];
            #pragma unroll
            for (int jj = 0; jj < 4; ++jj) kk[jj] = Ks[(4 * tx + jj) * QST + d];
            #pragma unroll
            for (int i = 0; i < 4; ++i)
                #pragma unroll
                for (int jj = 0; jj < 4; ++jj)
                    s[i][jj] = fmaf(a[i], kk[jj], s[i][jj]);
        }

        if (j == qb) {   // causal mask only on diagonal tile
            #pragma unroll
            for (int i = 0; i < 4; ++i)
                #pragma unroll
                for (int jj = 0; jj < 4; ++jj)
                    if (kb + 4 * tx + jj > qbase + 4 * ty + i) s[i][jj] = -INFINITY;
        }

        // Online softmax per row (row spread over the 16 tx lanes)
        #pragma unroll
        for (int i = 0; i < 4; ++i) {
            float mx = fmaxf(fmaxf(s[i][0], s[i][1]), fmaxf(s[i][2], s[i][3]));
            #pragma unroll
            for (int off = 8; off; off >>= 1)
                mx = fmaxf(mx, __shfl_xor_sync(0xffffffffu, mx, off));
            float mnew  = fmaxf(m[i], mx);
            float alpha = __expf(m[i] - mnew);
            m[i] = mnew;
            float rs = 0.f;
            #pragma unroll
            for (int jj = 0; jj < 4; ++jj) {
                float p = __expf(s[i][jj] - mnew);
                s[i][jj] = p;
                rs += p;
            }
            #pragma unroll
            for (int off = 8; off; off >>= 1)
                rs += __shfl_xor_sync(0xffffffffu, rs, off);
            l[i] = l[i] * alpha + rs;
            #pragma unroll
            for (int jj = 0; jj < 4; ++jj) o[i][jj] *= alpha;
            *(float4*)&Ps[(4 * ty + i) * PST + 4 * tx] =
                make_float4(s[i][0], s[i][1], s[i][2], s[i][3]);
        }
        __syncthreads();

        // O += P * V
        #pragma unroll 8
        for (int c = 0; c < BKV; ++c) {
            float p[4], v[4];
            #pragma unroll
            for (int i = 0; i < 4; ++i)  p[i] = Ps[(4 * ty + i) * PST + c];
            #pragma unroll
            for (int jj = 0; jj < 4; ++jj) v[jj] = Vs[c * QST + 4 * tx + jj];
            #pragma unroll
            for (int i = 0; i < 4; ++i)
                #pragma unroll
                for (int jj = 0; jj < 4; ++jj)
                    o[i][jj] = fmaf(p[i], v[jj], o[i][jj]);
        }
        __syncthreads();
    }

    // Normalize + write O in [B,S,D] layout (head h occupies cols h*64..h*64+63)
    float* optr = out + ((size_t)b * Sv + qbase) * Dv + (size_t)h * HDv;
    #pragma unroll
    for (int i = 0; i < 4; ++i) {
        float inv = 1.f / l[i];
        *(float4*)(optr + (size_t)(4 * ty + i) * Dv + 4 * tx) =
            make_float4(o[i][0] * inv, o[i][1] * inv, o[i][2] * inv, o[i][3] * inv);
    }
}

// ---------------------------------------------------------------------------
extern "C" void kernel_launch(void* const* d_in, const int* in_sizes, int n_in,
                              void* d_out, int out_size)
{
    (void)in_sizes; (void)n_in; (void)out_size;
    const float* x     = (const float*)d_in[0];
    const float* w_qkv = (const float*)d_in[1];
    const float* w_out = (const float*)d_in[2];
    float* out = (float*)d_out;

    float *qkv_buf = nullptr, *o_buf = nullptr;
    cudaGetSymbolAddress((void**)&qkv_buf, g_qkv);
    cudaGetSymbolAddress((void**)&o_buf, g_o);

    cudaFuncSetAttribute(attn_kernel,
                         cudaFuncAttributeMaxDynamicSharedMemorySize, ATTN_SMEM);

    // 1) QKV projection: [4096,1024] x [3072,1024]^T -> g_qkv [4096,3072]
    dim3 g1(3 * Dv / BN, Mv / BM);
    sgemm_nt<<<g1, 256>>>(x, w_qkv, qkv_buf, Dv, 3 * Dv);

    // 2) Causal flash attention -> g_o [4096,1024]
    dim3 g2(Sv / BQ, Hv, Bv);
    attn_kernel<<<g2, 256, ATTN_SMEM>>>(qkv_buf, o_buf);

    // 3) Output projection: [4096,1024] x [1024,1024]^T -> out
    dim3 g3(Dv / BN, Mv / BM);
    sgemm_nt<<<g3, 256>>>(o_buf, w_out, out, Dv, Dv);
}

// round 3
// speedup vs baseline: 1.4206x; 1.4206x over previous
#include <cuda_runtime.h>
#include <cuda_bf16.h>
#include <math.h>
#include <stdint.h>

// Problem constants
#define Bv 2
#define Sv 2048
#define Dv 1024
#define Hv 16
#define HDv 64
#define Mv (Bv*Sv)   // 4096 rows

// ---------------------------------------------------------------------------
// Scratch (device globals: no allocation allowed)
// ---------------------------------------------------------------------------
__device__ float g_qkv[(size_t)Mv * 3 * Dv];   // [4096, 3072] fp32
__device__ float g_o[(size_t)Mv * Dv];         // [4096, 1024] fp32
__device__ __align__(16) __nv_bfloat16 g_xh[(size_t)Mv * Dv];
__device__ __align__(16) __nv_bfloat16 g_xl[(size_t)Mv * Dv];
__device__ __align__(16) __nv_bfloat16 g_wqh[(size_t)3 * Dv * Dv];
__device__ __align__(16) __nv_bfloat16 g_wql[(size_t)3 * Dv * Dv];
__device__ __align__(16) __nv_bfloat16 g_oh[(size_t)Mv * Dv];
__device__ __align__(16) __nv_bfloat16 g_ol[(size_t)Mv * Dv];
__device__ __align__(16) __nv_bfloat16 g_woh[(size_t)Dv * Dv];
__device__ __align__(16) __nv_bfloat16 g_wol[(size_t)Dv * Dv];

// ---------------------------------------------------------------------------
// PTX helpers
// ---------------------------------------------------------------------------
__device__ __forceinline__ uint32_t smem_u32(const void* p) {
    uint32_t a;
    asm("{ .reg .u64 t; cvta.to.shared.u64 t, %1; cvt.u32.u64 %0, t; }" : "=r"(a) : "l"(p));
    return a;
}
#define CP_ASYNC16(sm, g) \
    asm volatile("cp.async.cg.shared.global [%0], [%1], 16;" :: "r"(sm), "l"(g) : "memory")
#define CP_COMMIT() asm volatile("cp.async.commit_group;" ::: "memory")
#define CP_WAIT(n)  asm volatile("cp.async.wait_group %0;" :: "n"(n) : "memory")

#define LDSM_X4(r0, r1, r2, r3, addr) \
    asm volatile("ldmatrix.sync.aligned.m8n8.x4.shared.b16 {%0,%1,%2,%3}, [%4];" \
        : "=r"(r0), "=r"(r1), "=r"(r2), "=r"(r3) : "r"(addr))

#define MMA16816(d, a, b) \
    asm volatile("mma.sync.aligned.m16n8k16.row.col.f32.bf16.bf16.f32 " \
        "{%0,%1,%2,%3}, {%4,%5,%6,%7}, {%8,%9}, {%0,%1,%2,%3};" \
        : "+f"((d)[0]), "+f"((d)[1]), "+f"((d)[2]), "+f"((d)[3]) \
        : "r"((a)[0]), "r"((a)[1]), "r"((a)[2]), "r"((a)[3]), "r"((b)[0]), "r"((b)[1]))

// ---------------------------------------------------------------------------
// fp32 -> (bf16 hi, bf16 lo) split kernel
// ---------------------------------------------------------------------------
__global__ __launch_bounds__(256) void split_bf16(
    const float* __restrict__ in, __nv_bfloat16* __restrict__ hi,
    __nv_bfloat16* __restrict__ lo, int n4)
{
    int i = blockIdx.x * blockDim.x + threadIdx.x;
    if (i >= n4) return;
    float4 v = ((const float4*)in)[i];
    __nv_bfloat16 h0 = __float2bfloat16(v.x), h1 = __float2bfloat16(v.y);
    __nv_bfloat16 h2 = __float2bfloat16(v.z), h3 = __float2bfloat16(v.w);
    __nv_bfloat16 l0 = __float2bfloat16(v.x - __bfloat162float(h0));
    __nv_bfloat16 l1 = __float2bfloat16(v.y - __bfloat162float(h1));
    __nv_bfloat16 l2 = __float2bfloat16(v.z - __bfloat162float(h2));
    __nv_bfloat16 l3 = __float2bfloat16(v.w - __bfloat162float(h3));
    ushort4 hv, lv;
    hv.x = __bfloat16_as_ushort(h0); hv.y = __bfloat16_as_ushort(h1);
    hv.z = __bfloat16_as_ushort(h2); hv.w = __bfloat16_as_ushort(h3);
    lv.x = __bfloat16_as_ushort(l0); lv.y = __bfloat16_as_ushort(l1);
    lv.z = __bfloat16_as_ushort(l2); lv.w = __bfloat16_as_ushort(l3);
    ((ushort4*)hi)[i] = hv;
    ((ushort4*)lo)[i] = lv;
}

// ---------------------------------------------------------------------------
// mma.sync bf16x3 GEMM:  C[M,N] = A[M,K] * B[N,K]^T  (fp32-equivalent accuracy)
// 128x128x32 tile, 256 threads (8 warps, each 64x32), double-buffered cp.async.
// Smem tiles use 80-byte row stride: rows walk all eight 16B bank slots
// (80 mod 128 has period 8) -> conflict-free ldmatrix.
// ---------------------------------------------------------------------------
#define BM 128
#define BN 128
#define BKc 32
#define TROW 40                       // bf16 elements per smem row (80 B)
#define TILE_ELE (128 * TROW)         // elements per tile
#define TILE_BYT (TILE_ELE * 2)       // 10240 B
#define STAGE_BYT (4 * TILE_BYT)      // Ah, Al, Bh, Bl = 40960 B
#define GEMM_SMEM (2 * STAGE_BYT)     // 81920 B

__device__ __forceinline__ void load_stage(
    uint32_t sb, int s,
    const __nv_bfloat16* __restrict__ Ah, const __nv_bfloat16* __restrict__ Al,
    const __nv_bfloat16* __restrict__ Bh, const __nv_bfloat16* __restrict__ Bl,
    int bm, int bn, int k0, int K, int tid)
{
    const __nv_bfloat16* srcs[4] = {
        Ah + (size_t)bm * K, Al + (size_t)bm * K,
        Bh + (size_t)bn * K, Bl + (size_t)bn * K };
    uint32_t base = sb + s * STAGE_BYT;
    #pragma unroll
    for (int t = 0; t < 4; ++t) {
        const __nv_bfloat16* src = srcs[t];
        uint32_t tb = base + t * TILE_BYT;
        #pragma unroll
        for (int j = 0; j < 2; ++j) {
            int idx = tid + j * 256;        // 0..511
            int row = idx >> 2, ch = idx & 3;
            CP_ASYNC16(tb + row * 80 + ch * 16,
                       src + (size_t)row * K + k0 + ch * 8);
        }
    }
}

__global__ __launch_bounds__(256) void gemm_mma_bf16x3(
    const __nv_bfloat16* __restrict__ Ah, const __nv_bfloat16* __restrict__ Al,
    const __nv_bfloat16* __restrict__ Bh, const __nv_bfloat16* __restrict__ Bl,
    float* __restrict__ C, int K, int N)
{
    extern __shared__ char smem[];
    const uint32_t sb = smem_u32(smem);
    const int tid = threadIdx.x, wid = tid >> 5, lane = tid & 31;
    const int bm = blockIdx.y * BM, bn = blockIdx.x * BN;
    const int wm = (wid >> 2) * 64;   // warp row offset in tile
    const int wn = (wid & 3) * 32;    // warp col offset in tile

    float acc[4][4][4];
    #pragma unroll
    for (int i = 0; i < 4; ++i)
        #pragma unroll
        for (int j = 0; j < 4; ++j)
            #pragma unroll
            for (int q = 0; q < 4; ++q) acc[i][j][q] = 0.f;

    // per-lane ldmatrix base: row = lane&15, 16B column = lane>>4
    const uint32_t lrow = (lane & 15);
    const uint32_t lcol = (lane >> 4) * 16;

    const int NKB = K / BKc;
    load_stage(sb, 0, Ah, Al, Bh, Bl, bm, bn, 0, K, tid);
    CP_COMMIT();

    for (int kb = 0; kb < NKB; ++kb) {
        const int s = kb & 1;
        if (kb + 1 < NKB) {
            load_stage(sb, s ^ 1, Ah, Al, Bh, Bl, bm, bn, (kb + 1) * BKc, K, tid);
            CP_COMMIT();
            CP_WAIT(1);
        } else {
            CP_WAIT(0);
        }
        __syncthreads();

        const uint32_t stb = sb + s * STAGE_BYT;
        #pragma unroll
        for (int ks = 0; ks < 2; ++ks) {
            const uint32_t koff = ks * 32 + lcol;
            uint32_t ah[4][4], al[4][4], bh[2][4], bl[2][4];
            #pragma unroll
            for (int rt = 0; rt < 4; ++rt) {
                uint32_t ro = (wm + rt * 16 + lrow) * 80 + koff;
                LDSM_X4(ah[rt][0], ah[rt][1], ah[rt][2], ah[rt][3], stb + ro);
                LDSM_X4(al[rt][0], al[rt][1], al[rt][2], al[rt][3], stb + TILE_BYT + ro);
            }
            #pragma unroll
            for (int g = 0; g < 2; ++g) {
                uint32_t ro = (wn + g * 16 + lrow) * 80 + koff;
                LDSM_X4(bh[g][0], bh[g][1], bh[g][2], bh[g][3], stb + 2 * TILE_BYT + ro);
                LDSM_X4(bl[g][0], bl[g][1], bl[g][2], bl[g][3], stb + 3 * TILE_BYT + ro);
            }
            // b-frag for n8 tile (g, sub): sub 0 -> {r0, r2}, sub 1 -> {r1, r3}
            #pragma unroll
            for (int rt = 0; rt < 4; ++rt)
                #pragma unroll
                for (int g = 0; g < 2; ++g)
                    #pragma unroll
                    for (int sub = 0; sub < 2; ++sub) {
                        int ct = g * 2 + sub;
                        uint32_t bfh[2] = { bh[g][sub], bh[g][sub + 2] };
                        uint32_t bfl[2] = { bl[g][sub], bl[g][sub + 2] };
                        MMA16816(acc[rt][ct], ah[rt], bfh);   // Ah*Bh
                        MMA16816(acc[rt][ct], ah[rt], bfl);   // Ah*Bl
                        MMA16816(acc[rt][ct], al[rt], bfh);   // Al*Bh
                    }
        }
        __syncthreads();
    }

    // Epilogue: direct fp32 stores
    const int r0 = bm + wm + (lane >> 2);
    const int c0 = bn + wn + (lane & 3) * 2;
    #pragma unroll
    for (int rt = 0; rt < 4; ++rt)
        #pragma unroll
        for (int ct = 0; ct < 4; ++ct) {
            float* p0 = C + (size_t)(r0 + rt * 16) * N + c0 + ct * 8;
            *(float2*)p0 = make_float2(acc[rt][ct][0], acc[rt][ct][1]);
            float* p1 = p0 + 8 * N;
            *(float2*)p1 = make_float2(acc[rt][ct][2], acc[rt][ct][3]);
        }
}

// ---------------------------------------------------------------------------
// Flash attention (fp32, causal) — unchanged
// ---------------------------------------------------------------------------
#define BQ 64
#define BKV 64
#define QST 65
#define PST 68
#define ATTN_SMEM ((3 * BQ * QST + BQ * PST) * 4)

__global__ __launch_bounds__(256) void attn_kernel(
    const float* __restrict__ qkv, float* __restrict__ out)
{
    extern __shared__ float sm[];
    float* Qs = sm;
    float* Ks = Qs + BQ * QST;
    float* Vs = Ks + BKV * QST;
    float* Ps = Vs + BKV * QST;

    const int tid = threadIdx.x;
    const int tx = tid & 15;
    const int ty = tid >> 4;
    const int qb = blockIdx.x;
    const int h  = blockIdx.y;
    const int b  = blockIdx.z;
    const int qbase = qb * BQ;

    const size_t rstride = 3 * Dv;
    const float* qptr = qkv + ((size_t)b * Sv + qbase) * rstride + (size_t)h * HDv;
    const float* kptr = qkv + (size_t)b * Sv * rstride + Dv     + (size_t)h * HDv;
    const float* vptr = qkv + (size_t)b * Sv * rstride + 2 * Dv + (size_t)h * HDv;

    for (int idx = tid; idx < BQ * HDv; idx += 256) {
        int r = idx >> 6, d = idx & 63;
        Qs[r * QST + d] = qptr[(size_t)r * rstride + d] * 0.125f;
    }

    float o[4][4] = {};
    float m[4] = {-INFINITY, -INFINITY, -INFINITY, -INFINITY};
    float l[4] = {};

    __syncthreads();

    for (int j = 0; j <= qb; ++j) {
        const int kb = j * BKV;
        for (int idx = tid; idx < BKV * HDv; idx += 256) {
            int r = idx >> 6, d = idx & 63;
            Ks[r * QST + d] = kptr[(size_t)(kb + r) * rstride + d];
            Vs[r * QST + d] = vptr[(size_t)(kb + r) * rstride + d];
        }
        __syncthreads();

        float s[4][4] = {};
        #pragma unroll 8
        for (int d = 0; d < HDv; ++d) {
            float a[4], kk[4];
            #pragma unroll
            for (int i = 0; i < 4; ++i)  a[i]  = Qs[(4 * ty + i) * QST + d];
            #pragma unroll
            for (int jj = 0; jj < 4; ++jj) kk[jj] = Ks[(4 * tx + jj) * QST + d];
            #pragma unroll
            for (int i = 0; i < 4; ++i)
                #pragma unroll
                for (int jj = 0; jj < 4; ++jj)
                    s[i][jj] = fmaf(a[i], kk[jj], s[i][jj]);
        }

        if (j == qb) {
            #pragma unroll
            for (int i = 0; i < 4; ++i)
                #pragma unroll
                for (int jj = 0; jj < 4; ++jj)
                    if (kb + 4 * tx + jj > qbase + 4 * ty + i) s[i][jj] = -INFINITY;
        }

        #pragma unroll
        for (int i = 0; i < 4; ++i) {
            float mx = fmaxf(fmaxf(s[i][0], s[i][1]), fmaxf(s[i][2], s[i][3]));
            #pragma unroll
            for (int off = 8; off; off >>= 1)
                mx = fmaxf(mx, __shfl_xor_sync(0xffffffffu, mx, off));
            float mnew  = fmaxf(m[i], mx);
            float alpha = __expf(m[i] - mnew);
            m[i] = mnew;
            float rs = 0.f;
            #pragma unroll
            for (int jj = 0; jj < 4; ++jj) {
                float p = __expf(s[i][jj] - mnew);
                s[i][jj] = p;
                rs += p;
            }
            #pragma unroll
            for (int off = 8; off; off >>= 1)
                rs += __shfl_xor_sync(0xffffffffu, rs, off);
            l[i] = l[i] * alpha + rs;
            #pragma unroll
            for (int jj = 0; jj < 4; ++jj) o[i][jj] *= alpha;
            *(float4*)&Ps[(4 * ty + i) * PST + 4 * tx] =
                make_float4(s[i][0], s[i][1], s[i][2], s[i][3]);
        }
        __syncthreads();

        #pragma unroll 8
        for (int c = 0; c < BKV; ++c) {
            float p[4], v[4];
            #pragma unroll
            for (int i = 0; i < 4; ++i)  p[i] = Ps[(4 * ty + i) * PST + c];
            #pragma unroll
            for (int jj = 0; jj < 4; ++jj) v[jj] = Vs[c * QST + 4 * tx + jj];
            #pragma unroll
            for (int i = 0; i < 4; ++i)
                #pragma unroll
                for (int jj = 0; jj < 4; ++jj)
                    o[i][jj] = fmaf(p[i], v[jj], o[i][jj]);
        }
        __syncthreads();
    }

    float* optr = out + ((size_t)b * Sv + qbase) * Dv + (size_t)h * HDv;
    #pragma unroll
    for (int i = 0; i < 4; ++i) {
        float inv = 1.f / l[i];
        *(float4*)(optr + (size_t)(4 * ty + i) * Dv + 4 * tx) =
            make_float4(o[i][0] * inv, o[i][1] * inv, o[i][2] * inv, o[i][3] * inv);
    }
}

// ---------------------------------------------------------------------------
extern "C" void kernel_launch(void* const* d_in, const int* in_sizes, int n_in,
                              void* d_out, int out_size)
{
    (void)in_sizes; (void)n_in; (void)out_size;
    const float* x     = (const float*)d_in[0];
    const float* w_qkv = (const float*)d_in[1];
    const float* w_out = (const float*)d_in[2];
    float* out = (float*)d_out;

    float *qkv_buf, *o_buf;
    __nv_bfloat16 *xh, *xl, *wqh, *wql, *oh, *ol, *woh, *wol;
    cudaGetSymbolAddress((void**)&qkv_buf, g_qkv);
    cudaGetSymbolAddress((void**)&o_buf, g_o);
    cudaGetSymbolAddress((void**)&xh, g_xh);   cudaGetSymbolAddress((void**)&xl, g_xl);
    cudaGetSymbolAddress((void**)&wqh, g_wqh); cudaGetSymbolAddress((void**)&wql, g_wql);
    cudaGetSymbolAddress((void**)&oh, g_oh);   cudaGetSymbolAddress((void**)&ol, g_ol);
    cudaGetSymbolAddress((void**)&woh, g_woh); cudaGetSymbolAddress((void**)&wol, g_wol);

    cudaFuncSetAttribute(attn_kernel,
                         cudaFuncAttributeMaxDynamicSharedMemorySize, ATTN_SMEM);
    cudaFuncSetAttribute(gemm_mma_bf16x3,
                         cudaFuncAttributeMaxDynamicSharedMemorySize, GEMM_SMEM);

    // Split inputs into bf16 hi/lo
    {
        int n4 = (Mv * Dv) / 4;
        split_bf16<<<(n4 + 255) / 256, 256>>>(x, xh, xl, n4);
        n4 = (3 * Dv * Dv) / 4;
        split_bf16<<<(n4 + 255) / 256, 256>>>(w_qkv, wqh, wql, n4);
        n4 = (Dv * Dv) / 4;
        split_bf16<<<(n4 + 255) / 256, 256>>>(w_out, woh, wol, n4);
    }

    // 1) QKV projection: [4096,1024] x [3072,1024]^T -> g_qkv
    {
        dim3 g(3 * Dv / BN, Mv / BM);
        gemm_mma_bf16x3<<<g, 256, GEMM_SMEM>>>(xh, xl, wqh, wql, qkv_buf, Dv, 3 * Dv);
    }

    // 2) Causal flash attention (fp32)
    {
        dim3 g(Sv / BQ, Hv, Bv);
        attn_kernel<<<g, 256, ATTN_SMEM>>>(qkv_buf, o_buf);
    }

    // 3) Split attention output, then output projection
    {
        int n4 = (Mv * Dv) / 4;
        split_bf16<<<(n4 + 255) / 256, 256>>>(o_buf, oh, ol, n4);
        dim3 g(Dv / BN, Mv / BM);
        gemm_mma_bf16x3<<<g, 256, GEMM_SMEM>>>(oh, ol, woh, wol, out, Dv, Dv);
    }
}

// round 4
// speedup vs baseline: 2.4304x; 1.7108x over previous
#include <cuda_runtime.h>
#include <cuda_bf16.h>
#include <math.h>
#include <stdint.h>

// Problem constants
#define Bv 2
#define Sv 2048
#define Dv 1024
#define Hv 16
#define HDv 64
#define Mv (Bv*Sv)   // 4096 rows

// ---------------------------------------------------------------------------
// Scratch (device globals: no allocation allowed)
// ---------------------------------------------------------------------------
__device__ __align__(16) __nv_bfloat16 g_xh[(size_t)Mv * Dv];
__device__ __align__(16) __nv_bfloat16 g_xl[(size_t)Mv * Dv];
__device__ __align__(16) __nv_bfloat16 g_wqh[(size_t)3 * Dv * Dv];
__device__ __align__(16) __nv_bfloat16 g_wql[(size_t)3 * Dv * Dv];
__device__ __align__(16) __nv_bfloat16 g_qkvh[(size_t)Mv * 3 * Dv];
__device__ __align__(16) __nv_bfloat16 g_qkvl[(size_t)Mv * 3 * Dv];
__device__ __align__(16) __nv_bfloat16 g_oh[(size_t)Mv * Dv];
__device__ __align__(16) __nv_bfloat16 g_ol[(size_t)Mv * Dv];
__device__ __align__(16) __nv_bfloat16 g_woh[(size_t)Dv * Dv];
__device__ __align__(16) __nv_bfloat16 g_wol[(size_t)Dv * Dv];

// ---------------------------------------------------------------------------
// PTX helpers
// ---------------------------------------------------------------------------
__device__ __forceinline__ uint32_t smem_u32(const void* p) {
    uint32_t a;
    asm("{ .reg .u64 t; cvta.to.shared.u64 t, %1; cvt.u32.u64 %0, t; }" : "=r"(a) : "l"(p));
    return a;
}
#define CP_ASYNC16(sm, g) \
    asm volatile("cp.async.cg.shared.global [%0], [%1], 16;" :: "r"(sm), "l"(g) : "memory")
#define CP_COMMIT() asm volatile("cp.async.commit_group;" ::: "memory")
#define CP_WAIT(n)  asm volatile("cp.async.wait_group %0;" :: "n"(n) : "memory")

#define LDSM_X4(r0, r1, r2, r3, addr) \
    asm volatile("ldmatrix.sync.aligned.m8n8.x4.shared.b16 {%0,%1,%2,%3}, [%4];" \
        : "=r"(r0), "=r"(r1), "=r"(r2), "=r"(r3) : "r"(addr))
#define LDSM_X4_T(r0, r1, r2, r3, addr) \
    asm volatile("ldmatrix.sync.aligned.m8n8.x4.trans.shared.b16 {%0,%1,%2,%3}, [%4];" \
        : "=r"(r0), "=r"(r1), "=r"(r2), "=r"(r3) : "r"(addr))

#define MMA16816(d, a, b) \
    asm volatile("mma.sync.aligned.m16n8k16.row.col.f32.bf16.bf16.f32 " \
        "{%0,%1,%2,%3}, {%4,%5,%6,%7}, {%8,%9}, {%0,%1,%2,%3};" \
        : "+f"((d)[0]), "+f"((d)[1]), "+f"((d)[2]), "+f"((d)[3]) \
        : "r"((a)[0]), "r"((a)[1]), "r"((a)[2]), "r"((a)[3]), "r"((b)[0]), "r"((b)[1]))

// pack(lo, hi) -> bf16x2 register (hi in upper 16 bits)
__device__ __forceinline__ uint32_t packbf(float lo, float hi) {
    uint32_t r;
    asm("cvt.rn.bf16x2.f32 %0, %1, %2;" : "=r"(r) : "f"(hi), "f"(lo));
    return r;
}
// residual of a prior packbf
__device__ __forceinline__ uint32_t packres(uint32_t h, float lo, float hi) {
    float lof = __uint_as_float(h << 16);
    float hif = __uint_as_float(h & 0xFFFF0000u);
    return packbf(lo - lof, hi - hif);
}

// ---------------------------------------------------------------------------
// fp32 -> (bf16 hi, bf16 lo) split kernel
// ---------------------------------------------------------------------------
__global__ __launch_bounds__(256) void split_bf16(
    const float* __restrict__ in, __nv_bfloat16* __restrict__ hi,
    __nv_bfloat16* __restrict__ lo, int n4)
{
    int i = blockIdx.x * blockDim.x + threadIdx.x;
    if (i >= n4) return;
    float4 v = ((const float4*)in)[i];
    uint32_t h0 = packbf(v.x, v.y), h1 = packbf(v.z, v.w);
    uint32_t l0 = packres(h0, v.x, v.y), l1 = packres(h1, v.z, v.w);
    ((uint2*)hi)[i] = make_uint2(h0, h1);
    ((uint2*)lo)[i] = make_uint2(l0, l1);
}

// ---------------------------------------------------------------------------
// mma.sync bf16x3 GEMM:  C[M,N] = A[M,K] * B[N,K]^T
// 128x128x32 tile, 256 threads (8 warps, each 64x32), double-buffered cp.async.
// WB=1: write bf16 hi/lo outputs; WB=0: write fp32.
// ---------------------------------------------------------------------------
#define BM 128
#define BN 128
#define BKc 32
#define TILE_BYT (128 * 80)           // 80B row stride
#define STAGE_BYT (4 * TILE_BYT)
#define GEMM_SMEM (2 * STAGE_BYT)     // 81920 B

__device__ __forceinline__ void load_stage(
    uint32_t sb, int s,
    const __nv_bfloat16* __restrict__ Ah, const __nv_bfloat16* __restrict__ Al,
    const __nv_bfloat16* __restrict__ Bh, const __nv_bfloat16* __restrict__ Bl,
    int bm, int bn, int k0, int K, int tid)
{
    const __nv_bfloat16* srcs[4] = {
        Ah + (size_t)bm * K, Al + (size_t)bm * K,
        Bh + (size_t)bn * K, Bl + (size_t)bn * K };
    uint32_t base = sb + s * STAGE_BYT;
    #pragma unroll
    for (int t = 0; t < 4; ++t) {
        const __nv_bfloat16* src = srcs[t];
        uint32_t tb = base + t * TILE_BYT;
        #pragma unroll
        for (int j = 0; j < 2; ++j) {
            int idx = tid + j * 256;
            int row = idx >> 2, ch = idx & 3;
            CP_ASYNC16(tb + row * 80 + ch * 16,
                       src + (size_t)row * K + k0 + ch * 8);
        }
    }
}

template<int WB>
__global__ __launch_bounds__(256) void gemm_mma_bf16x3(
    const __nv_bfloat16* __restrict__ Ah, const __nv_bfloat16* __restrict__ Al,
    const __nv_bfloat16* __restrict__ Bh, const __nv_bfloat16* __restrict__ Bl,
    float* __restrict__ C, __nv_bfloat16* __restrict__ Ch,
    __nv_bfloat16* __restrict__ Cl, int K, int N)
{
    extern __shared__ char smem[];
    const uint32_t sb = smem_u32(smem);
    const int tid = threadIdx.x, wid = tid >> 5, lane = tid & 31;
    const int bm = blockIdx.y * BM, bn = blockIdx.x * BN;
    const int wm = (wid >> 2) * 64;
    const int wn = (wid & 3) * 32;

    float acc[4][4][4];
    #pragma unroll
    for (int i = 0; i < 4; ++i)
        #pragma unroll
        for (int j = 0; j < 4; ++j)
            #pragma unroll
            for (int q = 0; q < 4; ++q) acc[i][j][q] = 0.f;

    const uint32_t lrow = (lane & 15);
    const uint32_t lcol = (lane >> 4) * 16;

    const int NKB = K / BKc;
    load_stage(sb, 0, Ah, Al, Bh, Bl, bm, bn, 0, K, tid);
    CP_COMMIT();

    for (int kb = 0; kb < NKB; ++kb) {
        const int s = kb & 1;
        if (kb + 1 < NKB) {
            load_stage(sb, s ^ 1, Ah, Al, Bh, Bl, bm, bn, (kb + 1) * BKc, K, tid);
            CP_COMMIT();
            CP_WAIT(1);
        } else {
            CP_WAIT(0);
        }
        __syncthreads();

        const uint32_t stb = sb + s * STAGE_BYT;
        #pragma unroll
        for (int ks = 0; ks < 2; ++ks) {
            const uint32_t koff = ks * 32 + lcol;
            uint32_t ah[4][4], al[4][4], bh[2][4], bl[2][4];
            #pragma unroll
            for (int rt = 0; rt < 4; ++rt) {
                uint32_t ro = (wm + rt * 16 + lrow) * 80 + koff;
                LDSM_X4(ah[rt][0], ah[rt][1], ah[rt][2], ah[rt][3], stb + ro);
                LDSM_X4(al[rt][0], al[rt][1], al[rt][2], al[rt][3], stb + TILE_BYT + ro);
            }
            #pragma unroll
            for (int g = 0; g < 2; ++g) {
                uint32_t ro = (wn + g * 16 + lrow) * 80 + koff;
                LDSM_X4(bh[g][0], bh[g][1], bh[g][2], bh[g][3], stb + 2 * TILE_BYT + ro);
                LDSM_X4(bl[g][0], bl[g][1], bl[g][2], bl[g][3], stb + 3 * TILE_BYT + ro);
            }
            #pragma unroll
            for (int rt = 0; rt < 4; ++rt)
                #pragma unroll
                for (int g = 0; g < 2; ++g)
                    #pragma unroll
                    for (int sub = 0; sub < 2; ++sub) {
                        int ct = g * 2 + sub;
                        uint32_t bfh[2] = { bh[g][sub], bh[g][sub + 2] };
                        uint32_t bfl[2] = { bl[g][sub], bl[g][sub + 2] };
                        MMA16816(acc[rt][ct], ah[rt], bfh);
                        MMA16816(acc[rt][ct], ah[rt], bfl);
                        MMA16816(acc[rt][ct], al[rt], bfh);
                    }
        }
        __syncthreads();
    }

    const int r0 = bm + wm + (lane >> 2);
    const int c0 = bn + wn + (lane & 3) * 2;
    #pragma unroll
    for (int rt = 0; rt < 4; ++rt)
        #pragma unroll
        for (int ct = 0; ct < 4; ++ct) {
            size_t i0 = (size_t)(r0 + rt * 16) * N + c0 + ct * 8;
            size_t i1 = i0 + (size_t)8 * N;
            if (WB) {
                uint32_t p0 = packbf(acc[rt][ct][0], acc[rt][ct][1]);
                uint32_t p1 = packbf(acc[rt][ct][2], acc[rt][ct][3]);
                *(uint32_t*)&Ch[i0] = p0;
                *(uint32_t*)&Ch[i1] = p1;
                *(uint32_t*)&Cl[i0] = packres(p0, acc[rt][ct][0], acc[rt][ct][1]);
                *(uint32_t*)&Cl[i1] = packres(p1, acc[rt][ct][2], acc[rt][ct][3]);
            } else {
                *(float2*)&C[i0] = make_float2(acc[rt][ct][0], acc[rt][ct][1]);
                *(float2*)&C[i1] = make_float2(acc[rt][ct][2], acc[rt][ct][3]);
            }
        }
}

// ---------------------------------------------------------------------------
// Flash attention with mma.sync bf16x3. CTA: 128 q-rows x 64 kv tile, 8 warps.
// Q/K/V hi+lo in smem (144B row stride), K/V double-buffered via cp.async.
// P stays in registers (acc->A-fragment layout identity).
// ---------------------------------------------------------------------------
#define BQa 128
#define BKVa 64
#define TST 144
#define SQH 0
#define SQL (128 * TST)
#define KVB (2 * 128 * TST)
#define KVSTG (4 * 64 * TST)
#define ATTN_SMEM (KVB + 2 * KVSTG)   // 110592 B

__global__ __launch_bounds__(256) void attn_mma(
    const __nv_bfloat16* __restrict__ qkvh, const __nv_bfloat16* __restrict__ qkvl,
    __nv_bfloat16* __restrict__ oh, __nv_bfloat16* __restrict__ ol)
{
    extern __shared__ char smem[];
    const uint32_t sb = smem_u32(smem);
    const int tid = threadIdx.x, wid = tid >> 5, lane = tid & 31;
    const int qi = (int)gridDim.x - 1 - (int)blockIdx.x;   // heavy tiles first
    const int h = blockIdx.y, b = blockIdx.z;
    const int qbase = qi * BQa;
    const int wq = wid * 16;
    const uint32_t lrow = lane & 15, lcol = (lane >> 4) * 16;
    const size_t ld = 3 * Dv;

    // Load Q tile (hi, lo)
    {
        const size_t base = ((size_t)b * Sv + qbase) * ld + (size_t)h * HDv;
        #pragma unroll
        for (int i = 0; i < 8; ++i) {
            int idx = tid + i * 256;            // 2 tiles * 128 rows * 8 chunks
            int t = idx >> 10, rr = (idx >> 3) & 127, ch = idx & 7;
            const __nv_bfloat16* src = (t ? qkvl : qkvh) + base + (size_t)rr * ld + ch * 8;
            CP_ASYNC16(sb + (t ? SQL : SQH) + rr * TST + ch * 16, src);
        }
    }

    const int ntiles = 2 * (qi + 1);
    // prologue: KV tile 0 -> stage 0
    {
        const size_t kbase = ((size_t)b * Sv) * ld + Dv + (size_t)h * HDv;
        #pragma unroll
        for (int i = 0; i < 8; ++i) {
            int idx = tid + i * 256;            // 4 tiles * 64 rows * 8 chunks
            int t = idx >> 9, rr = (idx >> 3) & 63, ch = idx & 7;
            size_t gb = kbase + ((t < 2) ? 0 : Dv);
            const __nv_bfloat16* src = ((t & 1) ? qkvl : qkvh) + gb + (size_t)rr * ld + ch * 8;
            CP_ASYNC16(sb + KVB + t * (64 * TST) + rr * TST + ch * 16, src);
        }
    }
    CP_COMMIT();

    float s[8][4], o[8][4];
    #pragma unroll
    for (int t = 0; t < 8; ++t)
        #pragma unroll
        for (int e = 0; e < 4; ++e) o[t][e] = 0.f;
    float m0 = -1e30f, m1 = -1e30f, l0 = 0.f, l1 = 0.f;

    for (int j = 0; j < ntiles; ++j) {
        const int stg = j & 1;
        if (j + 1 < ntiles) {
            const size_t kbase = ((size_t)b * Sv + (j + 1) * BKVa) * ld + Dv + (size_t)h * HDv;
            uint32_t s0 = sb + KVB + (stg ^ 1) * KVSTG;
            #pragma unroll
            for (int i = 0; i < 8; ++i) {
                int idx = tid + i * 256;
                int t = idx >> 9, rr = (idx >> 3) & 63, ch = idx & 7;
                size_t gb = kbase + ((t < 2) ? 0 : Dv);
                const __nv_bfloat16* src = ((t & 1) ? qkvl : qkvh) + gb + (size_t)rr * ld + ch * 8;
                CP_ASYNC16(s0 + t * (64 * TST) + rr * TST + ch * 16, src);
            }
            CP_COMMIT();
            CP_WAIT(1);
        } else {
            CP_WAIT(0);
        }
        __syncthreads();

        const uint32_t kh_b = sb + KVB + stg * KVSTG;
        const uint32_t kl_b = kh_b + 64 * TST;
        const uint32_t vh_b = kh_b + 2 * 64 * TST;
        const uint32_t vl_b = kh_b + 3 * 64 * TST;

        // S = Q K^T (bf16x3)
        #pragma unroll
        for (int t = 0; t < 8; ++t)
            #pragma unroll
            for (int e = 0; e < 4; ++e) s[t][e] = 0.f;
        #pragma unroll
        for (int dc = 0; dc < 4; ++dc) {
            uint32_t qoff = (wq + lrow) * TST + dc * 32 + lcol;
            uint32_t qh[4], ql[4];
            LDSM_X4(qh[0], qh[1], qh[2], qh[3], sb + SQH + qoff);
            LDSM_X4(ql[0], ql[1], ql[2], ql[3], sb + SQL + qoff);
            #pragma unroll
            for (int ng = 0; ng < 4; ++ng) {
                uint32_t koff = (ng * 16 + lrow) * TST + dc * 32 + lcol;
                uint32_t kh[4], kl[4];
                LDSM_X4(kh[0], kh[1], kh[2], kh[3], kh_b + koff);
                LDSM_X4(kl[0], kl[1], kl[2], kl[3], kl_b + koff);
                uint32_t b0h[2] = { kh[0], kh[2] }, b1h[2] = { kh[1], kh[3] };
                uint32_t b0l[2] = { kl[0], kl[2] }, b1l[2] = { kl[1], kl[3] };
                MMA16816(s[2 * ng],     qh, b0h);
                MMA16816(s[2 * ng],     qh, b0l);
                MMA16816(s[2 * ng],     ql, b0h);
                MMA16816(s[2 * ng + 1], qh, b1h);
                MMA16816(s[2 * ng + 1], qh, b1l);
                MMA16816(s[2 * ng + 1], ql, b1h);
            }
        }

        // scale + causal mask
        const int row0 = qbase + wq + (lane >> 2);
        if (j * BKVa + BKVa - 1 > qbase + wq) {
            #pragma unroll
            for (int t = 0; t < 8; ++t) {
                int colb = j * BKVa + 8 * t + (lane & 3) * 2;
                #pragma unroll
                for (int e = 0; e < 4; ++e) {
                    int col = colb + (e & 1);
                    int row = (e < 2) ? row0 : row0 + 8;
                    s[t][e] = (col > row) ? -1e30f : s[t][e] * 0.125f;
                }
            }
        } else {
            #pragma unroll
            for (int t = 0; t < 8; ++t)
                #pragma unroll
                for (int e = 0; e < 4; ++e) s[t][e] *= 0.125f;
        }

        // online softmax (rows row0, row0+8)
        float mx0 = -1e30f, mx1 = -1e30f;
        #pragma unroll
        for (int t = 0; t < 8; ++t) {
            mx0 = fmaxf(mx0, fmaxf(s[t][0], s[t][1]));
            mx1 = fmaxf(mx1, fmaxf(s[t][2], s[t][3]));
        }
        mx0 = fmaxf(mx0, __shfl_xor_sync(0xffffffffu, mx0, 1));
        mx0 = fmaxf(mx0, __shfl_xor_sync(0xffffffffu, mx0, 2));
        mx1 = fmaxf(mx1, __shfl_xor_sync(0xffffffffu, mx1, 1));
        mx1 = fmaxf(mx1, __shfl_xor_sync(0xffffffffu, mx1, 2));
        float mn0 = fmaxf(m0, mx0), mn1 = fmaxf(m1, mx1);
        float a0 = __expf(m0 - mn0), a1 = __expf(m1 - mn1);
        m0 = mn0; m1 = mn1;
        float rs0 = 0.f, rs1 = 0.f;
        #pragma unroll
        for (int t = 0; t < 8; ++t) {
            s[t][0] = __expf(s[t][0] - mn0);
            s[t][1] = __expf(s[t][1] - mn0);
            s[t][2] = __expf(s[t][2] - mn1);
            s[t][3] = __expf(s[t][3] - mn1);
            rs0 += s[t][0] + s[t][1];
            rs1 += s[t][2] + s[t][3];
            o[t][0] *= a0; o[t][1] *= a0; o[t][2] *= a1; o[t][3] *= a1;
        }
        rs0 += __shfl_xor_sync(0xffffffffu, rs0, 1);
        rs0 += __shfl_xor_sync(0xffffffffu, rs0, 2);
        rs1 += __shfl_xor_sync(0xffffffffu, rs1, 1);
        rs1 += __shfl_xor_sync(0xffffffffu, rs1, 2);
        l0 = l0 * a0 + rs0;
        l1 = l1 * a1 + rs1;

        // O += P V (P in registers via acc->A layout identity; bf16x3)
        #pragma unroll
        for (int kc = 0; kc < 4; ++kc) {
            uint32_t pah[4], pal[4];
            pah[0] = packbf(s[2 * kc][0], s[2 * kc][1]);
            pah[1] = packbf(s[2 * kc][2], s[2 * kc][3]);
            pah[2] = packbf(s[2 * kc + 1][0], s[2 * kc + 1][1]);
            pah[3] = packbf(s[2 * kc + 1][2], s[2 * kc + 1][3]);
            pal[0] = packres(pah[0], s[2 * kc][0], s[2 * kc][1]);
            pal[1] = packres(pah[1], s[2 * kc][2], s[2 * kc][3]);
            pal[2] = packres(pah[2], s[2 * kc + 1][0], s[2 * kc + 1][1]);
            pal[3] = packres(pah[3], s[2 * kc + 1][2], s[2 * kc + 1][3]);
            #pragma unroll
            for (int ng = 0; ng < 4; ++ng) {
                uint32_t voff = (kc * 16 + lrow) * TST + ng * 32 + lcol;
                uint32_t vh[4], vl[4];
                LDSM_X4_T(vh[0], vh[1], vh[2], vh[3], vh_b + voff);
                LDSM_X4_T(vl[0], vl[1], vl[2], vl[3], vl_b + voff);
                uint32_t bv0h[2] = { vh[0], vh[1] }, bv1h[2] = { vh[2], vh[3] };
                uint32_t bv0l[2] = { vl[0], vl[1] }, bv1l[2] = { vl[2], vl[3] };
                MMA16816(o[2 * ng],     pah, bv0h);
                MMA16816(o[2 * ng],     pah, bv0l);
                MMA16816(o[2 * ng],     pal, bv0h);
                MMA16816(o[2 * ng + 1], pah, bv1h);
                MMA16816(o[2 * ng + 1], pah, bv1l);
                MMA16816(o[2 * ng + 1], pal, bv1h);
            }
        }
        __syncthreads();
    }

    // epilogue: O/l -> bf16 hi/lo at [b*S + q][h*64 + n]
    const float i0 = 1.f / l0, i1 = 1.f / l1;
    const size_t r0 = (size_t)b * Sv + qbase + wq + (lane >> 2);
    const int cb = h * HDv + (lane & 3) * 2;
    #pragma unroll
    for (int t = 0; t < 8; ++t) {
        size_t ia = r0 * Dv + cb + 8 * t;
        size_t ib = ia + (size_t)8 * Dv;
        float f0 = o[t][0] * i0, f1 = o[t][1] * i0;
        float f2 = o[t][2] * i1, f3 = o[t][3] * i1;
        uint32_t p0 = packbf(f0, f1), p1 = packbf(f2, f3);
        *(uint32_t*)&oh[ia] = p0;
        *(uint32_t*)&oh[ib] = p1;
        *(uint32_t*)&ol[ia] = packres(p0, f0, f1);
        *(uint32_t*)&ol[ib] = packres(p1, f2, f3);
    }
}

// ---------------------------------------------------------------------------
extern "C" void kernel_launch(void* const* d_in, const int* in_sizes, int n_in,
                              void* d_out, int out_size)
{
    (void)in_sizes; (void)n_in; (void)out_size;
    const float* x     = (const float*)d_in[0];
    const float* w_qkv = (const float*)d_in[1];
    const float* w_out = (const float*)d_in[2];
    float* out = (float*)d_out;

    __nv_bfloat16 *xh, *xl, *wqh, *wql, *qkvh, *qkvl, *oh, *ol, *woh, *wol;
    cudaGetSymbolAddress((void**)&xh, g_xh);     cudaGetSymbolAddress((void**)&xl, g_xl);
    cudaGetSymbolAddress((void**)&wqh, g_wqh);   cudaGetSymbolAddress((void**)&wql, g_wql);
    cudaGetSymbolAddress((void**)&qkvh, g_qkvh); cudaGetSymbolAddress((void**)&qkvl, g_qkvl);
    cudaGetSymbolAddress((void**)&oh, g_oh);     cudaGetSymbolAddress((void**)&ol, g_ol);
    cudaGetSymbolAddress((void**)&woh, g_woh);   cudaGetSymbolAddress((void**)&wol, g_wol);

    cudaFuncSetAttribute(attn_mma,
                         cudaFuncAttributeMaxDynamicSharedMemorySize, ATTN_SMEM);
    cudaFuncSetAttribute(gemm_mma_bf16x3<0>,
                         cudaFuncAttributeMaxDynamicSharedMemorySize, GEMM_SMEM);
    cudaFuncSetAttribute(gemm_mma_bf16x3<1>,
                         cudaFuncAttributeMaxDynamicSharedMemorySize, GEMM_SMEM);

    // Split inputs into bf16 hi/lo
    {
        int n4 = (Mv * Dv) / 4;
        split_bf16<<<(n4 + 255) / 256, 256>>>(x, xh, xl, n4);
        n4 = (3 * Dv * Dv) / 4;
        split_bf16<<<(n4 + 255) / 256, 256>>>(w_qkv, wqh, wql, n4);
        n4 = (Dv * Dv) / 4;
        split_bf16<<<(n4 + 255) / 256, 256>>>(w_out, woh, wol, n4);
    }

    // 1) QKV projection -> bf16 hi/lo qkv
    {
        dim3 g(3 * Dv / BN, Mv / BM);
        gemm_mma_bf16x3<1><<<g, 256, GEMM_SMEM>>>(
            xh, xl, wqh, wql, nullptr, qkvh, qkvl, Dv, 3 * Dv);
    }

    // 2) Causal flash attention (mma bf16x3) -> bf16 hi/lo O
    {
        dim3 g(Sv / BQa, Hv, Bv);
        attn_mma<<<g, 256, ATTN_SMEM>>>(qkvh, qkvl, oh, ol);
    }

    // 3) Output projection -> fp32 out
    {
        dim3 g(Dv / BN, Mv / BM);
        gemm_mma_bf16x3<0><<<g, 256, GEMM_SMEM>>>(
            oh, ol, woh, wol, out, nullptr, nullptr, Dv, Dv);
    }
}